// round 15
// baseline (speedup 1.0000x reference)
#include <cuda_runtime.h>
#include <math.h>
#include <stdint.h>

#define NF 26
#define ND 16
#define H1 256
#define H2 128
#define ROWS 64
#define EPSF 1e-5f
#define NT 256

#define AS 424      // A1 row stride (bf16): 848B, order-8 phase spread
#define HS 264      // h1 row stride (bf16): 528B

// byte offsets in dynamic smem
#define A_B      0u            // 64*848 = 54272 B ; h1 (64*528) reuses this region
#define AUX_B    54272u
#define SMEM_BYTES (54272u + 4096u)   // 58368 B; x2 CTAs fits easily

// fragment-direct packed weights: [ks][wn][lane][slot]
__device__ __align__(16) uint32_t W1f[26*4*32*16];   // 213 KB
__device__ __align__(16) uint32_t W2f[16*4*32*8];    // 64 KB

__device__ __forceinline__ uint32_t smem_u32(const void* p){
    uint32_t a;
    asm("{ .reg .u64 t; cvta.to.shared.u64 t, %1; cvt.u32.u64 %0, t; }" : "=r"(a) : "l"(p));
    return a;
}
__device__ __forceinline__ uint32_t bf2(float lo, float hi){
    uint32_t r; asm("cvt.rn.bf16x2.f32 %0, %1, %2;" : "=r"(r) : "f"(hi), "f"(lo)); return r;
}
__device__ __forceinline__ void mma_bf16(float* d, const uint32_t* a, const uint32_t* b){
    asm volatile("mma.sync.aligned.m16n8k16.row.col.f32.bf16.bf16.f32 "
        "{%0,%1,%2,%3}, {%4,%5,%6,%7}, {%8,%9}, {%0,%1,%2,%3};"
        : "+f"(d[0]), "+f"(d[1]), "+f"(d[2]), "+f"(d[3])
        : "r"(a[0]), "r"(a[1]), "r"(a[2]), "r"(a[3]), "r"(b[0]), "r"(b[1]));
}
__device__ __forceinline__ void ldm4(uint32_t* r, uint32_t addr){
    asm volatile("ldmatrix.sync.aligned.m8n8.x4.shared.b16 {%0,%1,%2,%3}, [%4];"
        : "=r"(r[0]), "=r"(r[1]), "=r"(r[2]), "=r"(r[3]) : "r"(addr));
}
__device__ __forceinline__ void sts4u(uint32_t addr, uint32_t a, uint32_t b, uint32_t c, uint32_t d){
    asm volatile("st.shared.v4.b32 [%0], {%1,%2,%3,%4};" :: "r"(addr), "r"(a), "r"(b), "r"(c), "r"(d));
}
__device__ __forceinline__ void sts1u(uint32_t addr, uint32_t v){
    asm volatile("st.shared.b32 [%0], %1;" :: "r"(addr), "r"(v));
}

// ---- pack W1/W2 into per-lane fragment-direct order ----
// B-frag (validated via ldm4t in R12-14): lane l (g=l>>2, t=l&3), tile nb, k-step ks:
//   frag_f = { B[ks*16 + f*8 + 2t][nb*8+g], B[ks*16 + f*8 + 2t + 1][nb*8+g] }
__global__ void pack_wf(const float* __restrict__ W1, const float* __restrict__ W2){
    int t = blockIdx.x * blockDim.x + threadIdx.x;
    if (t < 26*4*32*16) {
        int f   = t & 1;
        int nbl = (t >> 1) & 7;
        int l   = (t >> 4) & 31;
        int wn  = (t >> 9) & 3;
        int ks  = t >> 11;
        int g = l >> 2, tt = l & 3;
        int n = (wn*8 + nbl)*8 + g;
        int k = ks*16 + f*8 + 2*tt;
        W1f[t] = bf2(W1[k*H1 + n], W1[(k+1)*H1 + n]);
    } else {
        int t2 = t - 26*4*32*16;
        if (t2 < 16*4*32*8) {
            int f   = t2 & 1;
            int nbl = (t2 >> 1) & 3;
            int l   = (t2 >> 3) & 31;
            int wn  = (t2 >> 8) & 3;
            int ks  = t2 >> 10;
            int g = l >> 2, tt = l & 3;
            int n = (wn*4 + nbl)*8 + g;
            int k = ks*16 + f*8 + 2*tt;
            W2f[t2] = bf2(W2[k*H2 + n], W2[(k+1)*H2 + n]);
        }
    }
}

__global__ __launch_bounds__(NT, 2)
void deepfm_bf16q(const int* __restrict__ X, const float* __restrict__ emb1,
                  const float* __restrict__ emb2,
                  const float* __restrict__ b1g,
                  const float* __restrict__ g1, const float* __restrict__ be1,
                  const float* __restrict__ m1, const float* __restrict__ v1,
                  const float* __restrict__ b2g,
                  const float* __restrict__ g2, const float* __restrict__ be2,
                  const float* __restrict__ m2, const float* __restrict__ v2,
                  const float* __restrict__ W3, const float* __restrict__ b3,
                  float* __restrict__ out, int Btot, int V)
{
    extern __shared__ char smc[];
    float* auxf    = (float*)(smc + AUX_B);
    float* fm_s    = auxf;
    float* logit_s = auxf + 64;
    float* S1f     = auxf + 128;
    float* B1f     = auxf + 384;
    float* S2f     = auxf + 640;
    float* B2f     = auxf + 768;
    float* W3s     = auxf + 896;

    const int tid  = threadIdx.x;
    const int wid  = tid >> 5;
    const int lane = tid & 31;
    const int b0   = blockIdx.x * ROWS;
    const uint32_t smbase = smem_u32(smc);

    if (tid < 64) logit_s[tid] = 0.f;
    if (tid < 256) {
        float s = g1[tid] * rsqrtf(v1[tid] + EPSF);
        S1f[tid] = s; B1f[tid] = be1[tid] + (b1g[tid] - m1[tid]) * s;
        if (tid < 128) {
            float s2 = g2[tid] * rsqrtf(v2[tid] + EPSF);
            S2f[tid] = s2; B2f[tid] = be2[tid] + (b2g[tid] - m2[tid]) * s2;
            W3s[tid] = W3[tid];
        }
    }

    // ---- Phase 1: gather e2 -> A [row][k] bf16; FM exact fp32 in regs ----
    {
        const int gr = tid >> 2;        // 0..63
        const int fi = tid & 3;
        float s[ND], q[ND]; float fm1 = 0.f;
        #pragma unroll
        for (int d = 0; d < ND; d++) { s[d] = 0.f; q[d] = 0.f; }
        const int* xr = X + (size_t)(b0 + gr) * NF;
        #pragma unroll
        for (int j = 0; j < 7; j++) {
            int f = fi + 4*j;
            if (f < NF) {
                int idx = xr[f];
                fm1 += emb1[(size_t)f * V + idx];
                const float4* e = (const float4*)(emb2 + ((size_t)f * V + idx) * ND);
                float4 v0 = e[0], v1v = e[1], v2v = e[2], v3v = e[3];
                s[0]+=v0.x;  q[0]+=v0.x*v0.x;   s[1]+=v0.y;  q[1]+=v0.y*v0.y;
                s[2]+=v0.z;  q[2]+=v0.z*v0.z;   s[3]+=v0.w;  q[3]+=v0.w*v0.w;
                s[4]+=v1v.x; q[4]+=v1v.x*v1v.x; s[5]+=v1v.y; q[5]+=v1v.y*v1v.y;
                s[6]+=v1v.z; q[6]+=v1v.z*v1v.z; s[7]+=v1v.w; q[7]+=v1v.w*v1v.w;
                s[8]+=v2v.x; q[8]+=v2v.x*v2v.x; s[9]+=v2v.y; q[9]+=v2v.y*v2v.y;
                s[10]+=v2v.z;q[10]+=v2v.z*v2v.z;s[11]+=v2v.w;q[11]+=v2v.w*v2v.w;
                s[12]+=v3v.x;q[12]+=v3v.x*v3v.x;s[13]+=v3v.y;q[13]+=v3v.y*v3v.y;
                s[14]+=v3v.z;q[14]+=v3v.z*v3v.z;s[15]+=v3v.w;q[15]+=v3v.w*v3v.w;
                uint32_t ad = smbase + A_B + ((uint32_t)gr*AS + (uint32_t)f*16u)*2u;
                sts4u(ad,       bf2(v0.x, v0.y),  bf2(v0.z, v0.w),
                                bf2(v1v.x, v1v.y), bf2(v1v.z, v1v.w));
                sts4u(ad + 16u, bf2(v2v.x, v2v.y), bf2(v2v.z, v2v.w),
                                bf2(v3v.x, v3v.y), bf2(v3v.z, v3v.w));
            }
        }
        #pragma unroll
        for (int m = 1; m < 4; m <<= 1) {
            fm1 += __shfl_xor_sync(0xffffffffu, fm1, m);
            #pragma unroll
            for (int d = 0; d < ND; d++) {
                s[d] += __shfl_xor_sync(0xffffffffu, s[d], m);
                q[d] += __shfl_xor_sync(0xffffffffu, q[d], m);
            }
        }
        if (fi == 0) {
            float fm2 = 0.f;
            #pragma unroll
            for (int d = 0; d < ND; d++) fm2 += 0.5f*(s[d]*s[d] - q[d]);
            fm_s[gr] = fm1 + fm2;
        }
    }
    __syncthreads();

    // ---- GEMM1: 26 k16-steps, no barriers; warp = (2 x m16) x n64 ----
    const int wm = wid & 1, wn = wid >> 1;          // wn in 0..3
    const int l15 = lane & 15, lhi = lane >> 4;
    const int g  = lane >> 2, t4 = lane & 3;
    float acc[64];                                   // [mt][j][4]: mt<2, j<8
    #pragma unroll
    for (int i = 0; i < 64; i++) acc[i] = 0.f;
    {
        const uint32_t aln0 = smbase + A_B
            + (uint32_t)(wm*32 + l15)*(AS*2u) + (uint32_t)(lhi*8)*2u;
        const uint32_t aln1 = aln0 + 16u*(AS*2u);
        const uint4* wp = (const uint4*)W1f + (size_t)(wn*32 + lane)*4;
        #pragma unroll 2
        for (int ks = 0; ks < 26; ks++) {
            uint4 q0 = wp[0], q1 = wp[1], q2 = wp[2], q3 = wp[3];
            wp += 512;                               // 4 wn * 32 lanes * 4 uint4
            uint32_t a0[4], a1[4];
            ldm4(a0, aln0 + (uint32_t)(ks*16)*2u);
            ldm4(a1, aln1 + (uint32_t)(ks*16)*2u);
            uint32_t pk[16];
            pk[0]=q0.x; pk[1]=q0.y; pk[2]=q0.z; pk[3]=q0.w;
            pk[4]=q1.x; pk[5]=q1.y; pk[6]=q1.z; pk[7]=q1.w;
            pk[8]=q2.x; pk[9]=q2.y; pk[10]=q2.z; pk[11]=q2.w;
            pk[12]=q3.x; pk[13]=q3.y; pk[14]=q3.z; pk[15]=q3.w;
            #pragma unroll
            for (int j = 0; j < 8; j++) {
                mma_bf16(&acc[j*4],      a0, &pk[2*j]);
                mma_bf16(&acc[32 + j*4], a1, &pk[2*j]);
            }
        }
    }
    __syncthreads();     // all warps done reading A before h1 overwrite

    // ---- BN1 + ReLU -> h1 [64][HS] bf16 (reuses A region) ----
    {
        #pragma unroll
        for (int mt = 0; mt < 2; mt++) {
            int rb = wm*32 + mt*16 + g;
            #pragma unroll
            for (int nf = 0; nf < 8; nf++) {
                int c0 = wn*64 + nf*8 + 2*t4;
                int ix = mt*32 + nf*4;
                float Sa = S1f[c0],   Ba = B1f[c0];
                float Sb = S1f[c0+1], Bb = B1f[c0+1];
                float h00 = fmaxf(acc[ix+0]*Sa + Ba, 0.f);
                float h01 = fmaxf(acc[ix+1]*Sb + Bb, 0.f);
                float h10 = fmaxf(acc[ix+2]*Sa + Ba, 0.f);
                float h11 = fmaxf(acc[ix+3]*Sb + Bb, 0.f);
                uint32_t ad = smbase + A_B + ((uint32_t)rb*HS + (uint32_t)c0)*2u;
                sts1u(ad,            bf2(h00, h01));
                sts1u(ad + 8u*HS*2u, bf2(h10, h11));
            }
        }
    }
    __syncthreads();

    // ---- GEMM2: 16 k16-steps, no barriers; warp = (2 x m16) x n32 ----
    float acc2[32];
    #pragma unroll
    for (int i = 0; i < 32; i++) acc2[i] = 0.f;
    {
        const uint32_t aln0 = smbase + A_B
            + (uint32_t)(wm*32 + l15)*(HS*2u) + (uint32_t)(lhi*8)*2u;
        const uint32_t aln1 = aln0 + 16u*(HS*2u);
        const uint4* wp = (const uint4*)W2f + (size_t)(wn*32 + lane)*2;
        #pragma unroll 2
        for (int ks = 0; ks < 16; ks++) {
            uint4 q0 = wp[0], q1 = wp[1];
            wp += 256;                               // 4 wn * 32 lanes * 2 uint4
            uint32_t a0[4], a1[4];
            ldm4(a0, aln0 + (uint32_t)(ks*16)*2u);
            ldm4(a1, aln1 + (uint32_t)(ks*16)*2u);
            uint32_t pk[8];
            pk[0]=q0.x; pk[1]=q0.y; pk[2]=q0.z; pk[3]=q0.w;
            pk[4]=q1.x; pk[5]=q1.y; pk[6]=q1.z; pk[7]=q1.w;
            #pragma unroll
            for (int j = 0; j < 4; j++) {
                mma_bf16(&acc2[j*4],      a0, &pk[2*j]);
                mma_bf16(&acc2[16 + j*4], a1, &pk[2*j]);
            }
        }
    }

    // ---- BN2 + ReLU + W3 dot -> logits ----
    {
        #pragma unroll
        for (int mt = 0; mt < 2; mt++) {
            int rb = wm*32 + mt*16 + g;
            float sum0 = 0.f, sum1 = 0.f;
            #pragma unroll
            for (int nf = 0; nf < 4; nf++) {
                int c0 = wn*32 + nf*8 + 2*t4;
                int ix = mt*16 + nf*4;
                float Sa = S2f[c0],   Ba = B2f[c0],   wa = W3s[c0];
                float Sb = S2f[c0+1], Bb = B2f[c0+1], wb = W3s[c0+1];
                sum0 += fmaxf(acc2[ix+0]*Sa + Ba, 0.f)*wa + fmaxf(acc2[ix+1]*Sb + Bb, 0.f)*wb;
                sum1 += fmaxf(acc2[ix+2]*Sa + Ba, 0.f)*wa + fmaxf(acc2[ix+3]*Sb + Bb, 0.f)*wb;
            }
            atomicAdd(&logit_s[rb],     sum0);
            atomicAdd(&logit_s[rb + 8], sum1);
        }
    }
    __syncthreads();

    // ---- Epilogue ----
    if (tid < ROWS) {
        float x = logit_s[tid] + fm_s[tid] + b3[0];
        out[b0 + tid] = 1.f / (1.f + expf(-x));
    }
}

extern "C" void kernel_launch(void* const* d_in, const int* in_sizes, int n_in,
                              void* d_out, int out_size)
{
    const int*   X    = (const int*)  d_in[0];
    const float* emb1 = (const float*)d_in[1];
    const float* emb2 = (const float*)d_in[2];
    const float* W1   = (const float*)d_in[3];
    const float* b1   = (const float*)d_in[4];
    const float* g1   = (const float*)d_in[5];
    const float* be1  = (const float*)d_in[6];
    const float* m1   = (const float*)d_in[7];
    const float* v1   = (const float*)d_in[8];
    const float* W2   = (const float*)d_in[9];
    const float* b2   = (const float*)d_in[10];
    const float* g2   = (const float*)d_in[11];
    const float* be2  = (const float*)d_in[12];
    const float* m2   = (const float*)d_in[13];
    const float* v2   = (const float*)d_in[14];
    const float* W3   = (const float*)d_in[15];
    const float* b3   = (const float*)d_in[16];
    float* out = (float*)d_out;

    int B = in_sizes[0] / NF;
    int V = in_sizes[1] / NF;

    int packn = 26*4*32*16 + 16*4*32*8;
    pack_wf<<<(packn + 255)/256, 256>>>(W1, W2);
    cudaFuncSetAttribute(deepfm_bf16q, cudaFuncAttributeMaxDynamicSharedMemorySize, SMEM_BYTES);
    deepfm_bf16q<<<B/ROWS, NT, SMEM_BYTES>>>(X, emb1, emb2, b1, g1, be1, m1, v1,
                                             b2, g2, be2, m2, v2, W3, b3,
                                             out, B, V);
}